// round 2
// baseline (speedup 1.0000x reference)
#include <cuda_runtime.h>
#include <math.h>

#define FULL 0xffffffffu

// ---------------- scratch (__device__ globals; no runtime allocation) ----------------
__device__ __align__(16) float  g_W512[512*128];      // folded [Woff@Wq ; Wwt@Wq]
__device__ float                g_b512[512];
__device__ __align__(16) float  g_WoutT[192*128];     // Wout transposed [k][c]
__device__ __align__(16) float4 g_samp[8*16*4096];    // (h,s,p,n) -> (gx,gy,gz,aw)
__device__ __align__(16) float  g_v0p[262144*32];     // v0 transposed [voxel][32]
__device__ __align__(16) float  g_val1[32768*256];    // projected s=1 [voxel][8h*32]
__device__ __align__(16) float  g_val2[4096*256];
__device__ __align__(16) float  g_val3[512*256];
__device__ __align__(16) float  g_acc[4096*192];      // [n][192]
__device__ __align__(16) float  g_outbuf[128*4096];   // pre-norm [c][n]

// ---------------- K0: fold weights + transpose Wout ----------------
__global__ void k0_fold(const float* __restrict__ Woff, const float* __restrict__ Wwt,
                        const float* __restrict__ Wq,
                        const float* __restrict__ boff, const float* __restrict__ bwt,
                        const float* __restrict__ Wout) {
    const int j = blockIdx.x;    // 0..511
    const int c = threadIdx.x;   // 0..127
    const float* A = (j < 384) ? (Woff + j*192) : (Wwt + (j-384)*192);
    float s = 0.f;
    for (int m = 0; m < 192; m++) s += A[m] * Wq[m*128 + c];
    g_W512[j*128 + c] = s;
    if (c == 0) g_b512[j] = (j < 384) ? boff[j] : bwt[j-384];
    if (j < 192) g_WoutT[j*128 + c] = Wout[c*192 + j];
}

// ---------------- K1: per-voxel 512x128 GEMM + tanh + softmax -> g_samp ----------------
__global__ void __launch_bounds__(256) k1_offaw(const float* __restrict__ qf) {
    __shared__ float xs[128*16];
    __shared__ float sbuf[512*17];
    const int nb = blockIdx.x * 16;
    const int tid = threadIdx.x;
    for (int e = tid; e < 128*16; e += 256) {
        int k = e >> 4, v = e & 15;
        xs[e] = qf[k*4096 + nb + v];
    }
    __syncthreads();
    const int r0 = tid, r1 = tid + 256;
    float acc0[16], acc1[16];
    const float b0 = g_b512[r0], b1 = g_b512[r1];
#pragma unroll
    for (int v = 0; v < 16; v++) { acc0[v] = b0; acc1[v] = b1; }
    for (int kk = 0; kk < 128; kk += 4) {
        float4 wa4 = *(const float4*)&g_W512[r0*128 + kk];
        float4 wb4 = *(const float4*)&g_W512[r1*128 + kk];
        float wa[4] = {wa4.x, wa4.y, wa4.z, wa4.w};
        float wb[4] = {wb4.x, wb4.y, wb4.z, wb4.w};
#pragma unroll
        for (int j = 0; j < 4; j++) {
            const float4* xr = (const float4*)&xs[(kk + j) * 16];
#pragma unroll
            for (int v4 = 0; v4 < 4; v4++) {
                float4 xv = xr[v4];
                acc0[v4*4+0] += wa[j]*xv.x; acc0[v4*4+1] += wa[j]*xv.y;
                acc0[v4*4+2] += wa[j]*xv.z; acc0[v4*4+3] += wa[j]*xv.w;
                acc1[v4*4+0] += wb[j]*xv.x; acc1[v4*4+1] += wb[j]*xv.y;
                acc1[v4*4+2] += wb[j]*xv.z; acc1[v4*4+3] += wb[j]*xv.w;
            }
        }
    }
#pragma unroll
    for (int v = 0; v < 16; v++) { sbuf[r0*17 + v] = acc0[v]; sbuf[r1*17 + v] = acc1[v]; }
    __syncthreads();
    if (tid < 128) {
        const int h = tid >> 4, v = tid & 15;
        const int n = nb + v;
        const int wx = n & 15, hy = (n >> 4) & 15, dz = n >> 8;
        const float bgx = -1.f + (float)wx * (2.f/15.f);
        const float bgy = -1.f + (float)hy * (2.f/15.f);
        const float bgz = -1.f + (float)dz * (2.f/15.f);
        float e[16];
        float m = -1e30f;
#pragma unroll
        for (int j = 0; j < 16; j++) {
            e[j] = sbuf[(384 + h*16 + j)*17 + v];
            m = fmaxf(m, e[j]);
        }
        float sum = 0.f;
#pragma unroll
        for (int j = 0; j < 16; j++) { e[j] = expf(e[j] - m); sum += e[j]; }
        const float inv = 1.f / sum;
#pragma unroll
        for (int s = 0; s < 4; s++)
#pragma unroll
            for (int p = 0; p < 4; p++) {
                const int rb = ((h*4 + s)*4 + p) * 3;
                float ox = tanhf(sbuf[(rb+0)*17 + v]) * 0.35f;
                float oy = tanhf(sbuf[(rb+1)*17 + v]) * 0.35f;
                float oz = tanhf(sbuf[(rb+2)*17 + v]) * 0.35f;
                g_samp[((h*4 + s)*4 + p)*4096 + n] =
                    make_float4(bgx + ox, bgy + oy, bgz + oz, e[s*4 + p] * inv);
            }
    }
}

// ---------------- K2: transpose v0 [32][262144] -> [262144][32] ----------------
__global__ void __launch_bounds__(256) k2_packv0(const float* __restrict__ v0) {
    __shared__ float t[32*129];
    const int vb = blockIdx.x * 128;
    const int tid = threadIdx.x;
    for (int e = tid; e < 32*128; e += 256) {
        int c = e >> 7, v = e & 127;
        t[c*129 + v] = v0[c*262144 + vb + v];
    }
    __syncthreads();
    for (int e = tid; e < 1024; e += 256) {
        int v = e >> 3, q = e & 7;
        float4 o;
        o.x = t[(q*4 + 0)*129 + v];
        o.y = t[(q*4 + 1)*129 + v];
        o.z = t[(q*4 + 2)*129 + v];
        o.w = t[(q*4 + 3)*129 + v];
        *(float4*)&g_v0p[(vb + v)*32 + q*4] = o;
    }
}

// ---------------- K3: project+pack scales 1..3 -> [voxel][8h*32pad] ----------------
__global__ void __launch_bounds__(256) k3_proj(const float* __restrict__ vsrc,
                                               const float* __restrict__ Wv,
                                               int C, int Nv, float* __restrict__ outv) {
    __shared__ float xs[256*32];
    const int nb = blockIdx.x * 32;
    const int tid = threadIdx.x;
    for (int e = tid; e < C*32; e += 256) {
        int c = e >> 5, v = e & 31;
        xs[e] = vsrc[c*Nv + nb + v];
    }
    __syncthreads();
    if (tid < 192) {
        float acc[32];
#pragma unroll
        for (int v = 0; v < 32; v++) acc[v] = 0.f;
        for (int kk = 0; kk < C; kk += 4) {
            float4 w4 = *(const float4*)&Wv[tid*C + kk];
            float w[4] = {w4.x, w4.y, w4.z, w4.w};
#pragma unroll
            for (int j = 0; j < 4; j++) {
                const float4* xr = (const float4*)&xs[(kk + j) * 32];
#pragma unroll
                for (int v4 = 0; v4 < 8; v4++) {
                    float4 xv = xr[v4];
                    acc[v4*4+0] += w[j]*xv.x; acc[v4*4+1] += w[j]*xv.y;
                    acc[v4*4+2] += w[j]*xv.z; acc[v4*4+3] += w[j]*xv.w;
                }
            }
        }
        const int slot = (tid/24)*32 + (tid%24);
#pragma unroll
        for (int v = 0; v < 32; v++) outv[(nb + v)*256 + slot] = acc[v];
    } else {
        const int jj = tid - 192;                 // 64 pad slots: 8 heads x 8 pads
        const int slot = (jj >> 3)*32 + 24 + (jj & 7);
        for (int v = 0; v < 32; v++) outv[(nb + v)*256 + slot] = 0.f;
    }
}

// ---------------- K4: multi-scale deformable trilinear sampling ----------------
// warp = one (h, n). lanes: corner = lane>>2 (8 corners), quad = lane&3.
__global__ void __launch_bounds__(256) k4_sample(const float* __restrict__ Wv0) {
    __shared__ float sW0[192*33];
    __shared__ float chunks[8][4][32];
    const int tid = threadIdx.x;
    for (int e = tid; e < 192*32; e += 256) {
        int r = e >> 5, k = e & 31;
        sW0[r*33 + k] = Wv0[e];
    }
    __syncthreads();

    const int warp = tid >> 5, lane = tid & 31;
    const int gw = blockIdx.x*8 + warp;
    const int h = gw >> 12, n = gw & 4095;
    const int corner = lane >> 2, q = lane & 3;
    const int cx = corner & 1, cy = (corner >> 1) & 1, cz = corner >> 2;

    for (int s = 0; s < 4; s++) {
        const float* vptr; int S, stride, cofs;
        if      (s == 0) { vptr = g_v0p;  S = 64; stride = 32;  cofs = 0;    }
        else if (s == 1) { vptr = g_val1; S = 32; stride = 256; cofs = h*32; }
        else if (s == 2) { vptr = g_val2; S = 16; stride = 256; cofs = h*32; }
        else             { vptr = g_val3; S = 8;  stride = 256; cofs = h*32; }
        const float fS = (float)S;
        float4 accA = make_float4(0.f,0.f,0.f,0.f);
        float4 accB = make_float4(0.f,0.f,0.f,0.f);
#pragma unroll
        for (int p = 0; p < 4; p++) {
            float4 sp = g_samp[((h*4 + s)*4 + p)*4096 + n];
            float ix = fminf(fmaxf(((sp.x + 1.f)*fS - 1.f)*0.5f, 0.f), fS - 1.f);
            float iy = fminf(fmaxf(((sp.y + 1.f)*fS - 1.f)*0.5f, 0.f), fS - 1.f);
            float iz = fminf(fmaxf(((sp.z + 1.f)*fS - 1.f)*0.5f, 0.f), fS - 1.f);
            float x0f = floorf(ix), y0f = floorf(iy), z0f = floorf(iz);
            float wx = ix - x0f, wy = iy - y0f, wz = iz - z0f;
            int x0 = (int)x0f, y0 = (int)y0f, z0 = (int)z0f;
            int x1 = min(x0 + 1, S - 1), y1 = min(y0 + 1, S - 1), z1 = min(z0 + 1, S - 1);
            int xc = cx ? x1 : x0, yc = cy ? y1 : y0, zc = cz ? z1 : z0;
            float w = (cx ? wx : 1.f - wx) * (cy ? wy : 1.f - wy) * (cz ? wz : 1.f - wz) * sp.w;
            const float* ptr = vptr + (zc*S + yc)*S*stride + xc*stride + cofs + q*4;
            float4 a = *(const float4*)ptr;
            float4 b = *(const float4*)(ptr + 16);
            accA.x += w*a.x; accA.y += w*a.y; accA.z += w*a.z; accA.w += w*a.w;
            accB.x += w*b.x; accB.y += w*b.y; accB.z += w*b.z; accB.w += w*b.w;
        }
#pragma unroll
        for (int m = 4; m <= 16; m <<= 1) {
            accA.x += __shfl_xor_sync(FULL, accA.x, m);
            accA.y += __shfl_xor_sync(FULL, accA.y, m);
            accA.z += __shfl_xor_sync(FULL, accA.z, m);
            accA.w += __shfl_xor_sync(FULL, accA.w, m);
            accB.x += __shfl_xor_sync(FULL, accB.x, m);
            accB.y += __shfl_xor_sync(FULL, accB.y, m);
            accB.z += __shfl_xor_sync(FULL, accB.z, m);
            accB.w += __shfl_xor_sync(FULL, accB.w, m);
        }
        if (lane < 4) {
            *(float4*)&chunks[warp][s][q*4]      = accA;
            *(float4*)&chunks[warp][s][16 + q*4] = accB;
        }
    }
    __syncwarp();
    if (lane < 24) {
        const float* wr = &sW0[(h*24 + lane)*33];
        const float* c0 = chunks[warp][0];
        float o = 0.f;
#pragma unroll
        for (int k = 0; k < 32; k++) o += wr[k] * c0[k];
        o += chunks[warp][1][lane] + chunks[warp][2][lane] + chunks[warp][3][lane];
        g_acc[n*192 + h*24 + lane] = o;
    }
}

// ---------------- K5: output GEMM 128x192 @ [192][4096] ----------------
__global__ void __launch_bounds__(128) k5_out() {
    __shared__ float xs[192*36];
    const int tid = threadIdx.x;
    const int nb = blockIdx.x * 32;
    for (int idx = tid; idx < 32*192; idx += 128) {
        int v = idx / 192, k = idx - v*192;
        xs[k*36 + v] = g_acc[(nb + v)*192 + k];
    }
    __syncthreads();
    float acc[32];
#pragma unroll
    for (int v = 0; v < 32; v++) acc[v] = 0.f;
    for (int k = 0; k < 192; k++) {
        float w = g_WoutT[k*128 + tid];
        const float4* xr = (const float4*)&xs[k*36];
#pragma unroll
        for (int v4 = 0; v4 < 8; v4++) {
            float4 x = xr[v4];
            acc[v4*4+0] += w*x.x; acc[v4*4+1] += w*x.y;
            acc[v4*4+2] += w*x.z; acc[v4*4+3] += w*x.w;
        }
    }
    float* orow = &g_outbuf[tid*4096 + nb];
#pragma unroll
    for (int v4 = 0; v4 < 8; v4++)
        *(float4*)&orow[v4*4] = make_float4(acc[v4*4], acc[v4*4+1], acc[v4*4+2], acc[v4*4+3]);
}

// ---------------- K6: InstanceNorm per channel ----------------
__global__ void __launch_bounds__(256) k6_norm(const float* __restrict__ gamma,
                                               const float* __restrict__ beta,
                                               float* __restrict__ out) {
    const int c = blockIdx.x, tid = threadIdx.x;
    const float* row = &g_outbuf[c*4096];
    float s = 0.f, s2 = 0.f;
    for (int i = tid; i < 4096; i += 256) { float x = row[i]; s += x; s2 += x*x; }
#pragma unroll
    for (int m = 16; m > 0; m >>= 1) {
        s  += __shfl_xor_sync(FULL, s,  m);
        s2 += __shfl_xor_sync(FULL, s2, m);
    }
    __shared__ float rs[8], rq[8];
    __shared__ float smu, srstd;
    if ((tid & 31) == 0) { rs[tid >> 5] = s; rq[tid >> 5] = s2; }
    __syncthreads();
    if (tid == 0) {
        float ts = 0.f, tq = 0.f;
        for (int i = 0; i < 8; i++) { ts += rs[i]; tq += rq[i]; }
        float mu = ts * (1.f/4096.f);
        smu = mu;
        srstd = rsqrtf(tq * (1.f/4096.f) - mu*mu + 1e-5f);
    }
    __syncthreads();
    const float g = gamma[c] * srstd, b = beta[c], mu = smu;
    for (int i = tid; i < 4096; i += 256)
        out[c*4096 + i] = (row[i] - mu) * g + b;
}

// ---------------- launch ----------------
extern "C" void kernel_launch(void* const* d_in, const int* in_sizes, int n_in,
                              void* d_out, int out_size) {
    const float* qf    = (const float*)d_in[0];
    const float* v0    = (const float*)d_in[1];
    const float* v1    = (const float*)d_in[2];
    const float* v2    = (const float*)d_in[3];
    const float* v3    = (const float*)d_in[4];
    const float* Wq    = (const float*)d_in[5];
    const float* Wv0   = (const float*)d_in[6];
    const float* Wv1   = (const float*)d_in[7];
    const float* Wv2   = (const float*)d_in[8];
    const float* Wv3   = (const float*)d_in[9];
    const float* Woff  = (const float*)d_in[10];
    const float* boff  = (const float*)d_in[11];
    const float* Wwt   = (const float*)d_in[12];
    const float* bwt   = (const float*)d_in[13];
    const float* Wout  = (const float*)d_in[14];
    const float* gamma = (const float*)d_in[15];
    const float* beta  = (const float*)d_in[16];
    float* out = (float*)d_out;

    float *p_v1, *p_v2, *p_v3;
    cudaGetSymbolAddress((void**)&p_v1, g_val1);
    cudaGetSymbolAddress((void**)&p_v2, g_val2);
    cudaGetSymbolAddress((void**)&p_v3, g_val3);

    k0_fold<<<512, 128>>>(Woff, Wwt, Wq, boff, bwt, Wout);
    k1_offaw<<<256, 256>>>(qf);
    k2_packv0<<<2048, 256>>>(v0);
    k3_proj<<<1024, 256>>>(v1, Wv1, 64,  32768, p_v1);
    k3_proj<<<128,  256>>>(v2, Wv2, 128, 4096,  p_v2);
    k3_proj<<<16,   256>>>(v3, Wv3, 256, 512,   p_v3);
    k4_sample<<<4096, 256>>>(Wv0);
    k5_out<<<128, 128>>>();
    k6_norm<<<128, 256>>>(gamma, beta, out);
}

// round 3
// speedup vs baseline: 1.0661x; 1.0661x over previous
#include <cuda_runtime.h>
#include <cuda_fp16.h>
#include <math.h>

#define FULL 0xffffffffu

// ---------------- scratch (__device__ globals; no runtime allocation) ----------------
__device__ __align__(16) float  g_W512[512*128];      // folded [Woff@Wq ; Wwt@Wq]
__device__ float                g_b512[512];
__device__ __align__(16) float  g_WoutT[192*128];     // Wout transposed [k][c]
__device__ __align__(16) float4 g_samp[8*16*4096];    // (h,s,p,n) -> (gx,gy,gz,aw)
__device__ __align__(16) __half g_v0ph[262144*32];    // v0 transposed fp16 [voxel][32]
__device__ __align__(16) __half g_val1[32768*256];    // projected s=1 fp16 [voxel][8h*32]
__device__ __align__(16) __half g_val2[4096*256];
__device__ __align__(16) __half g_val3[512*256];
__device__ __align__(16) float  g_acc[4096*192];      // [n][192]
__device__ __align__(16) float  g_outbuf[128*4096];   // pre-norm [c][n]

// ---------------- K0: fold weights + transpose Wout ----------------
__global__ void k0_fold(const float* __restrict__ Woff, const float* __restrict__ Wwt,
                        const float* __restrict__ Wq,
                        const float* __restrict__ boff, const float* __restrict__ bwt,
                        const float* __restrict__ Wout) {
    const int j = blockIdx.x;    // 0..511
    const int c = threadIdx.x;   // 0..127
    const float* A = (j < 384) ? (Woff + j*192) : (Wwt + (j-384)*192);
    float s = 0.f;
    for (int m = 0; m < 192; m++) s += A[m] * Wq[m*128 + c];
    g_W512[j*128 + c] = s;
    if (c == 0) g_b512[j] = (j < 384) ? boff[j] : bwt[j-384];
    if (j < 192) g_WoutT[j*128 + c] = Wout[c*192 + j];
}

// ---------------- K1: per-voxel 512x128 GEMM + tanh + softmax -> g_samp ----------------
__global__ void __launch_bounds__(256) k1_offaw(const float* __restrict__ qf) {
    __shared__ float xs[128*16];
    __shared__ float sbuf[512*17];
    const int nb = blockIdx.x * 16;
    const int tid = threadIdx.x;
    for (int e = tid; e < 128*16; e += 256) {
        int k = e >> 4, v = e & 15;
        xs[e] = qf[k*4096 + nb + v];
    }
    __syncthreads();
    const int r0 = tid, r1 = tid + 256;
    float acc0[16], acc1[16];
    const float b0 = g_b512[r0], b1 = g_b512[r1];
#pragma unroll
    for (int v = 0; v < 16; v++) { acc0[v] = b0; acc1[v] = b1; }
    for (int kk = 0; kk < 128; kk += 4) {
        float4 wa4 = *(const float4*)&g_W512[r0*128 + kk];
        float4 wb4 = *(const float4*)&g_W512[r1*128 + kk];
        float wa[4] = {wa4.x, wa4.y, wa4.z, wa4.w};
        float wb[4] = {wb4.x, wb4.y, wb4.z, wb4.w};
#pragma unroll
        for (int j = 0; j < 4; j++) {
            const float4* xr = (const float4*)&xs[(kk + j) * 16];
#pragma unroll
            for (int v4 = 0; v4 < 4; v4++) {
                float4 xv = xr[v4];
                acc0[v4*4+0] += wa[j]*xv.x; acc0[v4*4+1] += wa[j]*xv.y;
                acc0[v4*4+2] += wa[j]*xv.z; acc0[v4*4+3] += wa[j]*xv.w;
                acc1[v4*4+0] += wb[j]*xv.x; acc1[v4*4+1] += wb[j]*xv.y;
                acc1[v4*4+2] += wb[j]*xv.z; acc1[v4*4+3] += wb[j]*xv.w;
            }
        }
    }
#pragma unroll
    for (int v = 0; v < 16; v++) { sbuf[r0*17 + v] = acc0[v]; sbuf[r1*17 + v] = acc1[v]; }
    __syncthreads();
    if (tid < 128) {
        const int h = tid >> 4, v = tid & 15;
        const int n = nb + v;
        const int wx = n & 15, hy = (n >> 4) & 15, dz = n >> 8;
        const float bgx = -1.f + (float)wx * (2.f/15.f);
        const float bgy = -1.f + (float)hy * (2.f/15.f);
        const float bgz = -1.f + (float)dz * (2.f/15.f);
        float e[16];
        float m = -1e30f;
#pragma unroll
        for (int j = 0; j < 16; j++) {
            e[j] = sbuf[(384 + h*16 + j)*17 + v];
            m = fmaxf(m, e[j]);
        }
        float sum = 0.f;
#pragma unroll
        for (int j = 0; j < 16; j++) { e[j] = expf(e[j] - m); sum += e[j]; }
        const float inv = 1.f / sum;
#pragma unroll
        for (int s = 0; s < 4; s++)
#pragma unroll
            for (int p = 0; p < 4; p++) {
                const int rb = ((h*4 + s)*4 + p) * 3;
                float ox = tanhf(sbuf[(rb+0)*17 + v]) * 0.35f;
                float oy = tanhf(sbuf[(rb+1)*17 + v]) * 0.35f;
                float oz = tanhf(sbuf[(rb+2)*17 + v]) * 0.35f;
                g_samp[((h*4 + s)*4 + p)*4096 + n] =
                    make_float4(bgx + ox, bgy + oy, bgz + oz, e[s*4 + p] * inv);
            }
    }
}

// ---------------- K2: transpose v0 [32][262144] -> fp16 [262144][32] ----------------
__global__ void __launch_bounds__(256) k2_packv0(const float* __restrict__ v0) {
    __shared__ float t[32*129];
    const int vb = blockIdx.x * 128;
    const int tid = threadIdx.x;
    for (int e = tid; e < 32*128; e += 256) {
        int c = e >> 7, v = e & 127;
        t[c*129 + v] = v0[c*262144 + vb + v];
    }
    __syncthreads();
    // 512 uint4 stores: each = 8 consecutive channels (fp16) of one voxel
    for (int e = tid; e < 512; e += 256) {
        int v = e >> 2, q = e & 3;
        union { uint4 u; __half2 h[4]; } o;
#pragma unroll
        for (int j = 0; j < 4; j++)
            o.h[j] = __floats2half2_rn(t[(q*8 + 2*j)*129 + v], t[(q*8 + 2*j + 1)*129 + v]);
        *reinterpret_cast<uint4*>(&g_v0ph[(vb + v)*32 + q*8]) = o.u;
    }
}

// ---------------- K3: project+pack scales 1..3 -> fp16 [voxel][8h*32pad] ----------------
__global__ void __launch_bounds__(256) k3_proj(const float* __restrict__ vsrc,
                                               const float* __restrict__ Wv,
                                               int C, int Nv, __half* __restrict__ outv) {
    __shared__ float xs[256*32];
    __shared__ __half st[32*256];   // staged fp16 output: 32 voxels x 256 slots
    const int nb = blockIdx.x * 32;
    const int tid = threadIdx.x;
    for (int e = tid; e < C*32; e += 256) {
        int c = e >> 5, v = e & 31;
        xs[e] = vsrc[c*Nv + nb + v];
    }
    __syncthreads();
    if (tid < 192) {
        float acc[32];
#pragma unroll
        for (int v = 0; v < 32; v++) acc[v] = 0.f;
        for (int kk = 0; kk < C; kk += 4) {
            float4 w4 = *(const float4*)&Wv[tid*C + kk];
            float w[4] = {w4.x, w4.y, w4.z, w4.w};
#pragma unroll
            for (int j = 0; j < 4; j++) {
                const float4* xr = (const float4*)&xs[(kk + j) * 32];
#pragma unroll
                for (int v4 = 0; v4 < 8; v4++) {
                    float4 xv = xr[v4];
                    acc[v4*4+0] += w[j]*xv.x; acc[v4*4+1] += w[j]*xv.y;
                    acc[v4*4+2] += w[j]*xv.z; acc[v4*4+3] += w[j]*xv.w;
                }
            }
        }
        const int slot = (tid/24)*32 + (tid%24);
#pragma unroll
        for (int v = 0; v < 32; v++) st[v*256 + slot] = __float2half_rn(acc[v]);
    } else {
        const int jj = tid - 192;                 // 64 pad slots: 8 heads x 8 pads
        const int slot = (jj >> 3)*32 + 24 + (jj & 7);
        const __half hz = __float2half_rn(0.f);
        for (int v = 0; v < 32; v++) st[v*256 + slot] = hz;
    }
    __syncthreads();
    // contiguous 16KB block copy: voxels nb..nb+31 are consecutive rows
    const uint4* src = reinterpret_cast<const uint4*>(st);
    uint4* dst = reinterpret_cast<uint4*>(outv + (size_t)nb*256);
    for (int i = tid; i < 1024; i += 256) dst[i] = src[i];
}

// ---------------- K4: multi-scale deformable trilinear sampling (fp16 values) ----------------
// warp = one (h, n). lanes: corner = lane>>2 (8 corners), q = lane&3 (8 channels each).
__global__ void __launch_bounds__(256) k4_sample(const float* __restrict__ Wv0) {
    __shared__ float sW0[192*33];
    __shared__ float chunks[8][4][32];
    const int tid = threadIdx.x;
    for (int e = tid; e < 192*32; e += 256) {
        int r = e >> 5, k = e & 31;
        sW0[r*33 + k] = Wv0[e];
    }
    __syncthreads();

    const int warp = tid >> 5, lane = tid & 31;
    const int gw = blockIdx.x*8 + warp;
    const int h = gw >> 12, n = gw & 4095;
    const int corner = lane >> 2, q = lane & 3;
    const int cx = corner & 1, cy = (corner >> 1) & 1, cz = corner >> 2;

    for (int s = 0; s < 4; s++) {
        const __half* vptr; int S, stride, cofs;
        if      (s == 0) { vptr = g_v0ph; S = 64; stride = 32;  cofs = 0;    }
        else if (s == 1) { vptr = g_val1; S = 32; stride = 256; cofs = h*32; }
        else if (s == 2) { vptr = g_val2; S = 16; stride = 256; cofs = h*32; }
        else             { vptr = g_val3; S = 8;  stride = 256; cofs = h*32; }
        const float fS = (float)S;
        float2 acc4[4];
#pragma unroll
        for (int j = 0; j < 4; j++) acc4[j] = make_float2(0.f, 0.f);
#pragma unroll
        for (int p = 0; p < 4; p++) {
            float4 sp = g_samp[((h*4 + s)*4 + p)*4096 + n];
            float ix = fminf(fmaxf(((sp.x + 1.f)*fS - 1.f)*0.5f, 0.f), fS - 1.f);
            float iy = fminf(fmaxf(((sp.y + 1.f)*fS - 1.f)*0.5f, 0.f), fS - 1.f);
            float iz = fminf(fmaxf(((sp.z + 1.f)*fS - 1.f)*0.5f, 0.f), fS - 1.f);
            float x0f = floorf(ix), y0f = floorf(iy), z0f = floorf(iz);
            float wx = ix - x0f, wy = iy - y0f, wz = iz - z0f;
            int x0 = (int)x0f, y0 = (int)y0f, z0 = (int)z0f;
            int x1 = min(x0 + 1, S - 1), y1 = min(y0 + 1, S - 1), z1 = min(z0 + 1, S - 1);
            int xc = cx ? x1 : x0, yc = cy ? y1 : y0, zc = cz ? z1 : z0;
            float w = (cx ? wx : 1.f - wx) * (cy ? wy : 1.f - wy) * (cz ? wz : 1.f - wz) * sp.w;
            union { uint4 u; __half2 hh[4]; } d;
            d.u = *reinterpret_cast<const uint4*>(vptr + (size_t)((zc*S + yc)*S + xc)*stride + cofs + q*8);
#pragma unroll
            for (int j = 0; j < 4; j++) {
                float2 f = __half22float2(d.hh[j]);
                acc4[j].x += w*f.x; acc4[j].y += w*f.y;
            }
        }
#pragma unroll
        for (int m = 4; m <= 16; m <<= 1) {
#pragma unroll
            for (int j = 0; j < 4; j++) {
                acc4[j].x += __shfl_xor_sync(FULL, acc4[j].x, m);
                acc4[j].y += __shfl_xor_sync(FULL, acc4[j].y, m);
            }
        }
        if (lane < 4) {
#pragma unroll
            for (int j = 0; j < 4; j++) {
                chunks[warp][s][q*8 + 2*j]     = acc4[j].x;
                chunks[warp][s][q*8 + 2*j + 1] = acc4[j].y;
            }
        }
    }
    __syncwarp();
    if (lane < 24) {
        const float* wr = &sW0[(h*24 + lane)*33];
        const float* c0 = chunks[warp][0];
        float o = 0.f;
#pragma unroll
        for (int k = 0; k < 32; k++) o += wr[k] * c0[k];
        o += chunks[warp][1][lane] + chunks[warp][2][lane] + chunks[warp][3][lane];
        g_acc[n*192 + h*24 + lane] = o;
    }
}

// ---------------- K5: output GEMM 128x192 @ [192][4096] ----------------
__global__ void __launch_bounds__(128) k5_out() {
    __shared__ float xs[192*36];
    const int tid = threadIdx.x;
    const int nb = blockIdx.x * 32;
    for (int idx = tid; idx < 32*192; idx += 128) {
        int v = idx / 192, k = idx - v*192;
        xs[k*36 + v] = g_acc[(nb + v)*192 + k];
    }
    __syncthreads();
    float acc[32];
#pragma unroll
    for (int v = 0; v < 32; v++) acc[v] = 0.f;
    for (int k = 0; k < 192; k++) {
        float w = g_WoutT[k*128 + tid];
        const float4* xr = (const float4*)&xs[k*36];
#pragma unroll
        for (int v4 = 0; v4 < 8; v4++) {
            float4 x = xr[v4];
            acc[v4*4+0] += w*x.x; acc[v4*4+1] += w*x.y;
            acc[v4*4+2] += w*x.z; acc[v4*4+3] += w*x.w;
        }
    }
    float* orow = &g_outbuf[tid*4096 + nb];
#pragma unroll
    for (int v4 = 0; v4 < 8; v4++)
        *(float4*)&orow[v4*4] = make_float4(acc[v4*4], acc[v4*4+1], acc[v4*4+2], acc[v4*4+3]);
}

// ---------------- K6: InstanceNorm per channel ----------------
__global__ void __launch_bounds__(256) k6_norm(const float* __restrict__ gamma,
                                               const float* __restrict__ beta,
                                               float* __restrict__ out) {
    const int c = blockIdx.x, tid = threadIdx.x;
    const float* row = &g_outbuf[c*4096];
    float s = 0.f, s2 = 0.f;
    for (int i = tid; i < 4096; i += 256) { float x = row[i]; s += x; s2 += x*x; }
#pragma unroll
    for (int m = 16; m > 0; m >>= 1) {
        s  += __shfl_xor_sync(FULL, s,  m);
        s2 += __shfl_xor_sync(FULL, s2, m);
    }
    __shared__ float rs[8], rq[8];
    __shared__ float smu, srstd;
    if ((tid & 31) == 0) { rs[tid >> 5] = s; rq[tid >> 5] = s2; }
    __syncthreads();
    if (tid == 0) {
        float ts = 0.f, tq = 0.f;
        for (int i = 0; i < 8; i++) { ts += rs[i]; tq += rq[i]; }
        float mu = ts * (1.f/4096.f);
        smu = mu;
        srstd = rsqrtf(tq * (1.f/4096.f) - mu*mu + 1e-5f);
    }
    __syncthreads();
    const float g = gamma[c] * srstd, b = beta[c], mu = smu;
    for (int i = tid; i < 4096; i += 256)
        out[c*4096 + i] = (row[i] - mu) * g + b;
}

// ---------------- launch ----------------
extern "C" void kernel_launch(void* const* d_in, const int* in_sizes, int n_in,
                              void* d_out, int out_size) {
    const float* qf    = (const float*)d_in[0];
    const float* v0    = (const float*)d_in[1];
    const float* v1    = (const float*)d_in[2];
    const float* v2    = (const float*)d_in[3];
    const float* v3    = (const float*)d_in[4];
    const float* Wq    = (const float*)d_in[5];
    const float* Wv0   = (const float*)d_in[6];
    const float* Wv1   = (const float*)d_in[7];
    const float* Wv2   = (const float*)d_in[8];
    const float* Wv3   = (const float*)d_in[9];
    const float* Woff  = (const float*)d_in[10];
    const float* boff  = (const float*)d_in[11];
    const float* Wwt   = (const float*)d_in[12];
    const float* bwt   = (const float*)d_in[13];
    const float* Wout  = (const float*)d_in[14];
    const float* gamma = (const float*)d_in[15];
    const float* beta  = (const float*)d_in[16];
    float* out = (float*)d_out;

    __half *p_v1, *p_v2, *p_v3;
    cudaGetSymbolAddress((void**)&p_v1, g_val1);
    cudaGetSymbolAddress((void**)&p_v2, g_val2);
    cudaGetSymbolAddress((void**)&p_v3, g_val3);

    k0_fold<<<512, 128>>>(Woff, Wwt, Wq, boff, bwt, Wout);
    k1_offaw<<<256, 256>>>(qf);
    k2_packv0<<<2048, 256>>>(v0);
    k3_proj<<<1024, 256>>>(v1, Wv1, 64,  32768, p_v1);
    k3_proj<<<128,  256>>>(v2, Wv2, 128, 4096,  p_v2);
    k3_proj<<<16,   256>>>(v3, Wv3, 256, 512,   p_v3);
    k4_sample<<<4096, 256>>>(Wv0);
    k5_out<<<128, 128>>>();
    k6_norm<<<128, 256>>>(gamma, beta, out);
}